// round 1
// baseline (speedup 1.0000x reference)
#include <cuda_runtime.h>
#include <math.h>

#define S_  2048
#define D_  4096
#define H_  32
#define HD_ 128
#define FF_ 11008

// ---------------- scratch (no allocations allowed) ----------------
__device__ float g_xn  [(size_t)S_ * D_];
__device__ float g_q   [(size_t)S_ * D_];
__device__ float g_k   [(size_t)S_ * D_];
__device__ float g_v   [(size_t)S_ * D_];
__device__ float g_attn[(size_t)S_ * D_];
__device__ float g_x2  [(size_t)S_ * D_];
__device__ float g_xn2 [(size_t)S_ * D_];
__device__ float g_gate[(size_t)S_ * FF_];
__device__ float g_up  [(size_t)S_ * FF_];

// ---------------- RMSNorm ----------------
__global__ __launch_bounds__(256) void rmsnorm_kernel(
    const float* __restrict__ x, const float* __restrict__ w, float* __restrict__ out)
{
    int row = blockIdx.x;
    const float4* xr = (const float4*)(x + (size_t)row * D_);
    float ss = 0.f;
    #pragma unroll 4
    for (int i = threadIdx.x; i < D_ / 4; i += 256) {
        float4 v = xr[i];
        ss += v.x * v.x + v.y * v.y + v.z * v.z + v.w * v.w;
    }
    __shared__ float red[8];
    #pragma unroll
    for (int o = 16; o; o >>= 1) ss += __shfl_xor_sync(0xffffffffu, ss, o);
    if ((threadIdx.x & 31) == 0) red[threadIdx.x >> 5] = ss;
    __syncthreads();
    if (threadIdx.x == 0) {
        float t = 0.f;
        #pragma unroll
        for (int i = 0; i < 8; i++) t += red[i];
        red[0] = rsqrtf(t / (float)D_ + 1e-5f);
    }
    __syncthreads();
    float inv = red[0];
    const float4* wr = (const float4*)w;
    float4* o4 = (float4*)(out + (size_t)row * D_);
    for (int i = threadIdx.x; i < D_ / 4; i += 256) {
        float4 v = xr[i], wv = wr[i];
        v.x = v.x * inv * wv.x;
        v.y = v.y * inv * wv.y;
        v.z = v.z * inv * wv.z;
        v.w = v.w * inv * wv.w;
        o4[i] = v;
    }
}

// ---------------- SGEMM: C = A[MxK] @ B[KxN] (+ residual) ----------------
// BM=BN=128, BK=16, 256 threads, 8x8 per-thread microtile.
template <bool RESID>
__global__ __launch_bounds__(256) void sgemm_kernel(
    int M, int N, int K,
    const float* __restrict__ A, const float* __restrict__ B,
    const float* __restrict__ Rsd, float* __restrict__ C)
{
    const int BM = 128, BN = 128, BK = 16;
    __shared__ float As[BK][BM];
    __shared__ float Bs[BK][BN];

    int tid = threadIdx.x;
    const float* Ab = A + (size_t)blockIdx.y * BM * K;
    const float* Bb = B + (size_t)blockIdx.x * BN;

    int aRow = tid >> 2;             // 0..63  (rows aRow, aRow+64)
    int aCol = (tid & 3) << 2;       // 0,4,8,12
    int bRow = tid >> 5;             // 0..7   (rows bRow, bRow+8)
    int bCol = (tid & 31) << 2;      // 0..124
    int tRow = (tid >> 4) << 3;
    int tCol = (tid & 15) << 3;

    float acc[8][8] = {};

    for (int k0 = 0; k0 < K; k0 += BK) {
        float4 a0 = *(const float4*)(Ab + (size_t)aRow * K + k0 + aCol);
        float4 a1 = *(const float4*)(Ab + (size_t)(aRow + 64) * K + k0 + aCol);
        float4 b0 = *(const float4*)(Bb + (size_t)(k0 + bRow) * N + bCol);
        float4 b1 = *(const float4*)(Bb + (size_t)(k0 + bRow + 8) * N + bCol);

        As[aCol + 0][aRow] = a0.x;  As[aCol + 1][aRow] = a0.y;
        As[aCol + 2][aRow] = a0.z;  As[aCol + 3][aRow] = a0.w;
        As[aCol + 0][aRow + 64] = a1.x;  As[aCol + 1][aRow + 64] = a1.y;
        As[aCol + 2][aRow + 64] = a1.z;  As[aCol + 3][aRow + 64] = a1.w;
        *(float4*)&Bs[bRow][bCol]     = b0;
        *(float4*)&Bs[bRow + 8][bCol] = b1;
        __syncthreads();

        #pragma unroll
        for (int kk = 0; kk < BK; kk++) {
            float regM[8], regN[8];
            *(float4*)(regM)     = *(float4*)&As[kk][tRow];
            *(float4*)(regM + 4) = *(float4*)&As[kk][tRow + 4];
            *(float4*)(regN)     = *(float4*)&Bs[kk][tCol];
            *(float4*)(regN + 4) = *(float4*)&Bs[kk][tCol + 4];
            #pragma unroll
            for (int i = 0; i < 8; i++)
                #pragma unroll
                for (int j = 0; j < 8; j++)
                    acc[i][j] = fmaf(regM[i], regN[j], acc[i][j]);
        }
        __syncthreads();
    }

    size_t crow0 = (size_t)blockIdx.y * BM + tRow;
    int    ccol0 = blockIdx.x * BN + tCol;
    #pragma unroll
    for (int i = 0; i < 8; i++) {
        float* cp = C + (crow0 + i) * N + ccol0;
        #pragma unroll
        for (int j = 0; j < 8; j += 4) {
            float4 v = make_float4(acc[i][j], acc[i][j + 1], acc[i][j + 2], acc[i][j + 3]);
            if (RESID) {
                float4 r = *(const float4*)(Rsd + (crow0 + i) * N + ccol0 + j);
                v.x += r.x; v.y += r.y; v.z += r.z; v.w += r.w;
            }
            *(float4*)(cp + j) = v;
        }
    }
}

// ---------------- RoPE (q and k in place) ----------------
__global__ void rope_kernel(float* __restrict__ q, float* __restrict__ k)
{
    int s = blockIdx.x;
    int j = threadIdx.x;   // 0..63 pair index
    // inv_freq = 10000^(-2j/128), computed in fp64 -> matches jnp fp32 table to <=1 ulp
    float inv = (float)exp((double)j * -0.14391156831212787);  // -(2/128)*ln(10000)
    float ang = (float)s * inv;
    float sn, cs;
    sincosf(ang, &sn, &cs);
    #pragma unroll 4
    for (int h = 0; h < H_; h++) {
        size_t base = ((size_t)s * H_ + h) * HD_ + 2 * j;
        float q1 = q[base], q2 = q[base + 1];
        q[base]     = q1 * cs - q2 * sn;
        q[base + 1] = q1 * sn + q2 * cs;
        float k1 = k[base], k2 = k[base + 1];
        k[base]     = k1 * cs - k2 * sn;
        k[base + 1] = k1 * sn + k2 * cs;
    }
}

// ---------------- Fused causal attention (flash style) ----------------
// BQ=BK=64, HD=128. One block per (q-tile, head). 256 threads.
#define QS_STRIDE 129
#define VS_STRIDE 132
#define SS_STRIDE 65
#define ATTN_SMEM ((2 * 64 * QS_STRIDE + 64 * VS_STRIDE + 64 * SS_STRIDE + 3 * 64) * 4)

__global__ __launch_bounds__(256) void attn_kernel(
    const float* __restrict__ Q, const float* __restrict__ Kg,
    const float* __restrict__ Vg, float* __restrict__ O)
{
    extern __shared__ float sm[];
    float* Qs   = sm;                        // [64][129]
    float* Ks   = Qs + 64 * QS_STRIDE;       // [64][129]
    float* Vs   = Ks + 64 * QS_STRIDE;       // [64][132]
    float* Ss   = Vs + 64 * VS_STRIDE;       // [64][65]
    float* m_sh = Ss + 64 * SS_STRIDE;
    float* l_sh = m_sh + 64;
    float* a_sh = l_sh + 64;

    int tid = threadIdx.x;
    int h   = blockIdx.y;
    int bq  = gridDim.x - 1 - blockIdx.x;    // long CTAs first
    int q0  = bq * 64;
    int tr  = tid >> 4;                      // 0..15
    int tc  = tid & 15;                      // 0..15

    // load Q tile
    for (int idx = tid; idx < 64 * 32; idx += 256) {
        int r = idx >> 5, c = (idx & 31) << 2;
        float4 v = *(const float4*)(Q + (size_t)(q0 + r) * D_ + h * HD_ + c);
        float* p = Qs + r * QS_STRIDE + c;
        p[0] = v.x; p[1] = v.y; p[2] = v.z; p[3] = v.w;
    }
    if (tid < 64) { m_sh[tid] = -INFINITY; l_sh[tid] = 0.f; }
    float Oa[4][8] = {};
    __syncthreads();

    const float scale = 0.08838834764831845f;  // 1/sqrt(128)

    for (int kt = 0; kt <= bq; kt++) {
        int k0 = kt * 64;
        // load K (scalar, pad 129) and V (vector, pad 132)
        for (int idx = tid; idx < 64 * 32; idx += 256) {
            int r = idx >> 5, c = (idx & 31) << 2;
            float4 kv = *(const float4*)(Kg + (size_t)(k0 + r) * D_ + h * HD_ + c);
            float* kp = Ks + r * QS_STRIDE + c;
            kp[0] = kv.x; kp[1] = kv.y; kp[2] = kv.z; kp[3] = kv.w;
            float4 vv = *(const float4*)(Vg + (size_t)(k0 + r) * D_ + h * HD_ + c);
            *(float4*)(Vs + r * VS_STRIDE + c) = vv;
        }
        __syncthreads();

        // S = Q K^T : 4x4 microtile per thread
        float sacc[4][4] = {};
        #pragma unroll 4
        for (int kk = 0; kk < HD_; kk++) {
            float qv[4], kv[4];
            #pragma unroll
            for (int i = 0; i < 4; i++) qv[i] = Qs[(tr * 4 + i) * QS_STRIDE + kk];
            #pragma unroll
            for (int j = 0; j < 4; j++) kv[j] = Ks[(tc * 4 + j) * QS_STRIDE + kk];
            #pragma unroll
            for (int i = 0; i < 4; i++)
                #pragma unroll
                for (int j = 0; j < 4; j++)
                    sacc[i][j] = fmaf(qv[i], kv[j], sacc[i][j]);
        }
        bool diag = (kt == bq);
        #pragma unroll
        for (int i = 0; i < 4; i++)
            #pragma unroll
            for (int j = 0; j < 4; j++) {
                float v = sacc[i][j] * scale;
                if (diag && (k0 + tc * 4 + j) > (q0 + tr * 4 + i)) v = -1e30f;
                Ss[(tr * 4 + i) * SS_STRIDE + tc * 4 + j] = v;
            }
        __syncthreads();

        // online softmax per row
        if (tid < 64) {
            float mold = m_sh[tid], mx = mold;
            float* Sr = Ss + tid * SS_STRIDE;
            #pragma unroll 8
            for (int j = 0; j < 64; j++) mx = fmaxf(mx, Sr[j]);
            float al = __expf(mold - mx);
            float sum = 0.f;
            #pragma unroll 8
            for (int j = 0; j < 64; j++) { float p = __expf(Sr[j] - mx); Sr[j] = p; sum += p; }
            l_sh[tid] = l_sh[tid] * al + sum;
            m_sh[tid] = mx;
            a_sh[tid] = al;
        }
        __syncthreads();

        // O = O*alpha + P @ V : 4 rows x 8 cols per thread
        #pragma unroll
        for (int i = 0; i < 4; i++) {
            float a = a_sh[tr * 4 + i];
            #pragma unroll
            for (int j = 0; j < 8; j++) Oa[i][j] *= a;
        }
        #pragma unroll 2
        for (int kk = 0; kk < 64; kk++) {
            float pv[4], vv[8];
            #pragma unroll
            for (int i = 0; i < 4; i++) pv[i] = Ss[(tr * 4 + i) * SS_STRIDE + kk];
            *(float4*)(vv)     = *(float4*)(Vs + kk * VS_STRIDE + tc * 8);
            *(float4*)(vv + 4) = *(float4*)(Vs + kk * VS_STRIDE + tc * 8 + 4);
            #pragma unroll
            for (int i = 0; i < 4; i++)
                #pragma unroll
                for (int j = 0; j < 8; j++)
                    Oa[i][j] = fmaf(pv[i], vv[j], Oa[i][j]);
        }
        __syncthreads();
    }

    // write O / l
    #pragma unroll
    for (int i = 0; i < 4; i++) {
        float inv = 1.0f / l_sh[tr * 4 + i];
        float* op = O + (size_t)(q0 + tr * 4 + i) * D_ + h * HD_ + tc * 8;
        float4 v0 = make_float4(Oa[i][0] * inv, Oa[i][1] * inv, Oa[i][2] * inv, Oa[i][3] * inv);
        float4 v1 = make_float4(Oa[i][4] * inv, Oa[i][5] * inv, Oa[i][6] * inv, Oa[i][7] * inv);
        *(float4*)(op)     = v0;
        *(float4*)(op + 4) = v1;
    }
}

// ---------------- SiLU(gate) * up, in place into gate ----------------
__global__ void silu_mul_kernel(float* __restrict__ g, const float* __restrict__ u, int n4)
{
    int i = blockIdx.x * blockDim.x + threadIdx.x;
    if (i < n4) {
        float4 gv = ((const float4*)g)[i];
        float4 uv = ((const float4*)u)[i];
        gv.x = gv.x / (1.f + __expf(-gv.x)) * uv.x;
        gv.y = gv.y / (1.f + __expf(-gv.y)) * uv.y;
        gv.z = gv.z / (1.f + __expf(-gv.z)) * uv.z;
        gv.w = gv.w / (1.f + __expf(-gv.w)) * uv.w;
        ((float4*)g)[i] = gv;
    }
}

// ---------------- launch ----------------
extern "C" void kernel_launch(void* const* d_in, const int* in_sizes, int n_in,
                              void* d_out, int out_size)
{
    const float* x      = (const float*)d_in[0];
    const float* ln_w   = (const float*)d_in[1];
    const float* ffln_w = (const float*)d_in[2];
    const float* wq     = (const float*)d_in[3];
    const float* wk     = (const float*)d_in[4];
    const float* wv     = (const float*)d_in[5];
    const float* wo     = (const float*)d_in[6];
    const float* wg     = (const float*)d_in[7];
    const float* w1     = (const float*)d_in[8];
    const float* w2     = (const float*)d_in[9];
    float* out = (float*)d_out;

    float *xn, *q, *k, *v, *attn, *x2, *xn2, *gate, *up;
    cudaGetSymbolAddress((void**)&xn,   g_xn);
    cudaGetSymbolAddress((void**)&q,    g_q);
    cudaGetSymbolAddress((void**)&k,    g_k);
    cudaGetSymbolAddress((void**)&v,    g_v);
    cudaGetSymbolAddress((void**)&attn, g_attn);
    cudaGetSymbolAddress((void**)&x2,   g_x2);
    cudaGetSymbolAddress((void**)&xn2,  g_xn2);
    cudaGetSymbolAddress((void**)&gate, g_gate);
    cudaGetSymbolAddress((void**)&up,   g_up);

    cudaFuncSetAttribute(attn_kernel, cudaFuncAttributeMaxDynamicSharedMemorySize, ATTN_SMEM);

    // xn = rmsnorm(x, ln_w)
    rmsnorm_kernel<<<S_, 256>>>(x, ln_w, xn);

    // q,k,v projections
    dim3 g44(D_ / 128, S_ / 128);
    sgemm_kernel<false><<<g44, 256>>>(S_, D_, D_, xn, wq, nullptr, q);
    sgemm_kernel<false><<<g44, 256>>>(S_, D_, D_, xn, wk, nullptr, k);
    sgemm_kernel<false><<<g44, 256>>>(S_, D_, D_, xn, wv, nullptr, v);

    // rope on q,k
    rope_kernel<<<S_, 64>>>(q, k);

    // attention
    attn_kernel<<<dim3(S_ / 64, H_), 256, ATTN_SMEM>>>(q, k, v, attn);

    // x2 = attn @ wo + x
    sgemm_kernel<true><<<g44, 256>>>(S_, D_, D_, attn, wo, x, x2);

    // xn2 = rmsnorm(x2, ff_ln_w)
    rmsnorm_kernel<<<S_, 256>>>(x2, ffln_w, xn2);

    // gate/up projections
    dim3 gff(FF_ / 128, S_ / 128);
    sgemm_kernel<false><<<gff, 256>>>(S_, FF_, D_, xn2, wg, nullptr, gate);
    sgemm_kernel<false><<<gff, 256>>>(S_, FF_, D_, xn2, w1, nullptr, up);

    // h = silu(gate) * up (into gate)
    int n4 = (S_ * FF_) / 4;
    silu_mul_kernel<<<(n4 + 255) / 256, 256>>>(gate, up, n4);

    // out = h @ w2 + x2
    sgemm_kernel<true><<<dim3(D_ / 128, S_ / 128), 256>>>(S_, D_, FF_, gate, w2, x2, out);
}

// round 3
// speedup vs baseline: 2.8371x; 2.8371x over previous
#include <cuda_runtime.h>
#include <cuda_fp16.h>
#include <cstdint>
#include <math.h>

#define S_  2048
#define D_  4096
#define H_  32
#define HD_ 128
#define FF_ 11008

// ---------------- scratch (no allocations allowed) ----------------
__device__ float g_xn  [(size_t)S_ * D_];
__device__ float g_q   [(size_t)S_ * D_];
__device__ float g_k   [(size_t)S_ * D_];
__device__ float g_v   [(size_t)S_ * D_];
__device__ float g_attn[(size_t)S_ * D_];
__device__ float g_x2  [(size_t)S_ * D_];
__device__ float g_xn2 [(size_t)S_ * D_];
__device__ float g_gate[(size_t)S_ * FF_];
__device__ float g_up  [(size_t)S_ * FF_];

// transposed + hi/lo split weights (fp16), layout [N, K] row-major
__device__ __half g_wqt_h[(size_t)D_ * D_];
__device__ __half g_wqt_l[(size_t)D_ * D_];
__device__ __half g_wkt_h[(size_t)D_ * D_];
__device__ __half g_wkt_l[(size_t)D_ * D_];
__device__ __half g_wvt_h[(size_t)D_ * D_];
__device__ __half g_wvt_l[(size_t)D_ * D_];
__device__ __half g_wot_h[(size_t)D_ * D_];
__device__ __half g_wot_l[(size_t)D_ * D_];
__device__ __half g_wgt_h[(size_t)FF_ * D_];
__device__ __half g_wgt_l[(size_t)FF_ * D_];
__device__ __half g_w1t_h[(size_t)FF_ * D_];
__device__ __half g_w1t_l[(size_t)FF_ * D_];
__device__ __half g_w2t_h[(size_t)D_ * FF_];
__device__ __half g_w2t_l[(size_t)D_ * FF_];

// activation hi/lo split scratch (reused sequentially)
__device__ __half g_a_h[(size_t)S_ * FF_];
__device__ __half g_a_l[(size_t)S_ * FF_];

// ---------------- asm helpers ----------------
__device__ __forceinline__ uint32_t smem_to_u32(const void* p) {
    uint32_t a;
    asm("{ .reg .u64 t; cvta.to.shared.u64 t, %1; cvt.u32.u64 %0, t; }" : "=r"(a) : "l"(p));
    return a;
}
__device__ __forceinline__ void cp16(uint32_t saddr, const void* gaddr) {
    asm volatile("cp.async.cg.shared.global [%0], [%1], 16;" :: "r"(saddr), "l"(gaddr));
}
#define CP_COMMIT() asm volatile("cp.async.commit_group;" ::: "memory")
#define CP_WAIT(n)  asm volatile("cp.async.wait_group %0;" :: "n"(n) : "memory")

#define LDSM_X4(r0, r1, r2, r3, addr) \
    asm volatile("ldmatrix.sync.aligned.m8n8.x4.shared.b16 {%0,%1,%2,%3}, [%4];" \
        : "=r"(r0), "=r"(r1), "=r"(r2), "=r"(r3) : "r"(addr))

#define MMA16816(d, a, b) \
    asm volatile("mma.sync.aligned.m16n8k16.row.col.f32.f16.f16.f32 " \
        "{%0,%1,%2,%3}, {%4,%5,%6,%7}, {%8,%9}, {%0,%1,%2,%3};" \
        : "+f"((d)[0]), "+f"((d)[1]), "+f"((d)[2]), "+f"((d)[3]) \
        : "r"((a)[0]), "r"((a)[1]), "r"((a)[2]), "r"((a)[3]), "r"((b)[0]), "r"((b)[1]))

// ---------------- weight transpose + hi/lo split (fp32 [K,N] -> fp16 h/l [N,K]) ----------------
__global__ __launch_bounds__(256) void wsplit_kernel(
    const float* __restrict__ W, __half* __restrict__ Wh,
    __half* __restrict__ Wl, int K, int N)
{
    __shared__ float t[32][33];
    int n0 = blockIdx.x * 32, k0 = blockIdx.y * 32;
    int tx = threadIdx.x, ty = threadIdx.y; // (32, 8)
    #pragma unroll
    for (int i = 0; i < 4; i++)
        t[ty + 8 * i][tx] = W[(size_t)(k0 + ty + 8 * i) * N + n0 + tx];
    __syncthreads();
    #pragma unroll
    for (int i = 0; i < 4; i++) {
        float v = t[tx][ty + 8 * i];
        __half hi = __float2half_rn(v);
        __half lo = __float2half_rn(v - __half2float(hi));
        size_t o = (size_t)(n0 + ty + 8 * i) * K + k0 + tx;
        Wh[o] = hi; Wl[o] = lo;
    }
}

// ---------------- activation hi/lo split (fp32 -> fp16 h/l, same layout) ----------------
__global__ void asplit_kernel(const float* __restrict__ in,
                              __half* __restrict__ h, __half* __restrict__ l, int n4)
{
    int i = blockIdx.x * blockDim.x + threadIdx.x;
    if (i < n4) {
        float4 v = ((const float4*)in)[i];
        __half h0 = __float2half_rn(v.x), h1 = __float2half_rn(v.y);
        __half h2 = __float2half_rn(v.z), h3 = __float2half_rn(v.w);
        __half l0 = __float2half_rn(v.x - __half2float(h0));
        __half l1 = __float2half_rn(v.y - __half2float(h1));
        __half l2 = __float2half_rn(v.z - __half2float(h2));
        __half l3 = __float2half_rn(v.w - __half2float(h3));
        ((__half2*)h)[i * 2]     = __halves2half2(h0, h1);
        ((__half2*)h)[i * 2 + 1] = __halves2half2(h2, h3);
        ((__half2*)l)[i * 2]     = __halves2half2(l0, l1);
        ((__half2*)l)[i * 2 + 1] = __halves2half2(l2, l3);
    }
}

// ---------------- HMMA GEMM: C[M,N] = A @ Bt^T (+resid), 3-term fp16 split ----------------
// CTA 128x128, BK=64, 3-stage cp.async pipeline, 256 thr (8 warps, warp tile 32x64).
#define STAGES 3
#define OPBYTES 16384                 // 128 rows x 64 f16 = 16KB
#define STAGE_BYTES (4 * OPBYTES)     // Ah | Al | Bh | Bl
#define HGEMM_SMEM (STAGES * STAGE_BYTES)

template <bool RESID>
__global__ __launch_bounds__(256) void hgemm(
    int M, int N, int K,
    const __half* __restrict__ Ah, const __half* __restrict__ Al,
    const __half* __restrict__ Bh, const __half* __restrict__ Bl,
    const float* __restrict__ Rsd, float* __restrict__ C)
{
    extern __shared__ __align__(1024) char smem[];
    const int tid  = threadIdx.x;
    const int wid  = tid >> 5;
    const int lane = tid & 31;
    const int m0 = blockIdx.x * 128;
    const int n0 = blockIdx.y * 128;
    const int nk = K >> 6;
    const uint32_t sbase = smem_to_u32(smem);

    const int wm = (wid & 3) * 32;   // warp M offset
    const int wn = (wid >> 2) * 64;  // warp N offset

    const __half* Abase_h = Ah + (size_t)m0 * K;
    const __half* Abase_l = Al + (size_t)m0 * K;
    const __half* Bbase_h = Bh + (size_t)n0 * K;
    const __half* Bbase_l = Bl + (size_t)n0 * K;

    // per-thread load coords (4 chunks of 16B per operand)
    int lrow[4], lcc[4];
    uint32_t lsoff[4];
    #pragma unroll
    for (int t = 0; t < 4; t++) {
        int c = tid + t * 256;
        lrow[t] = c >> 3;
        lcc[t]  = c & 7;
        lsoff[t] = lrow[t] * 128 + (((lcc[t] ^ (lrow[t] & 7))) << 4);
    }

    #define ISSUE(s, kt) do { \
        uint32_t sb_ = sbase + (s) * STAGE_BYTES; \
        size_t kofs_ = (size_t)(kt) << 6; \
        _Pragma("unroll") \
        for (int t = 0; t < 4; t++) { \
            size_t go_ = (size_t)lrow[t] * K + kofs_ + lcc[t] * 8; \
            uint32_t so_ = sb_ + lsoff[t]; \
            cp16(so_,               Abase_h + go_); \
            cp16(so_ + OPBYTES,     Abase_l + go_); \
            cp16(so_ + 2 * OPBYTES, Bbase_h + go_); \
            cp16(so_ + 3 * OPBYTES, Bbase_l + go_); \
        } \
    } while (0)

    float acc[2][8][4] = {};

    // prologue: stages 0..STAGES-2
    #pragma unroll
    for (int s = 0; s < STAGES - 1; s++) { ISSUE(s, s); CP_COMMIT(); }

    const int mat = lane >> 3, rin = lane & 7;

    for (int i = 0; i < nk; i++) {
        CP_WAIT(STAGES - 2);
        __syncthreads();
        if (i + STAGES - 1 < nk) { ISSUE((i + STAGES - 1) % STAGES, i + STAGES - 1); }
        CP_COMMIT();

        uint32_t stg = sbase + (i % STAGES) * STAGE_BYTES;
        #pragma unroll
        for (int ks = 0; ks < 4; ks++) {
            int ks2 = ks << 1;
            uint32_t fa_h[2][4], fa_l[2][4], fb_h[8][2], fb_l[8][2];
            #pragma unroll
            for (int mt = 0; mt < 2; mt++) {
                int m = wm + mt * 16 + ((mat & 1) << 3) + rin;
                uint32_t ad = stg + m * 128 + (((ks2 + (mat >> 1)) ^ (m & 7)) << 4);
                LDSM_X4(fa_h[mt][0], fa_h[mt][1], fa_h[mt][2], fa_h[mt][3], ad);
                LDSM_X4(fa_l[mt][0], fa_l[mt][1], fa_l[mt][2], fa_l[mt][3], ad + OPBYTES);
            }
            #pragma unroll
            for (int p = 0; p < 4; p++) {
                int n = wn + p * 16 + ((mat >> 1) << 3) + rin;
                uint32_t bd = stg + 2 * OPBYTES + n * 128 + (((ks2 + (mat & 1)) ^ (n & 7)) << 4);
                uint32_t r0, r1, r2, r3;
                LDSM_X4(r0, r1, r2, r3, bd);
                fb_h[p * 2][0] = r0; fb_h[p * 2][1] = r1;
                fb_h[p * 2 + 1][0] = r2; fb_h[p * 2 + 1][1] = r3;
                LDSM_X4(r0, r1, r2, r3, bd + OPBYTES);
                fb_l[p * 2][0] = r0; fb_l[p * 2][1] = r1;
                fb_l[p * 2 + 1][0] = r2; fb_l[p * 2 + 1][1] = r3;
            }
            #pragma unroll
            for (int mt = 0; mt < 2; mt++)
                #pragma unroll
                for (int nt = 0; nt < 8; nt++) {
                    MMA16816(acc[mt][nt], fa_h[mt], fb_h[nt]);
                    MMA16816(acc[mt][nt], fa_h[mt], fb_l[nt]);
                    MMA16816(acc[mt][nt], fa_l[mt], fb_h[nt]);
                }
        }
        __syncthreads();
    }
    #undef ISSUE

    // epilogue
    int qr = lane >> 2, qc = (lane & 3) << 1;
    #pragma unroll
    for (int mt = 0; mt < 2; mt++) {
        #pragma unroll
        for (int nt = 0; nt < 8; nt++) {
            int r0 = m0 + wm + mt * 16 + qr;
            int cc = n0 + wn + nt * 8 + qc;
            float2 v0 = make_float2(acc[mt][nt][0], acc[mt][nt][1]);
            float2 v1 = make_float2(acc[mt][nt][2], acc[mt][nt][3]);
            if (RESID) {
                float2 a = *(const float2*)(Rsd + (size_t)r0 * N + cc);
                float2 b = *(const float2*)(Rsd + (size_t)(r0 + 8) * N + cc);
                v0.x += a.x; v0.y += a.y; v1.x += b.x; v1.y += b.y;
            }
            *(float2*)(C + (size_t)r0 * N + cc)       = v0;
            *(float2*)(C + (size_t)(r0 + 8) * N + cc) = v1;
        }
    }
}

// ---------------- RMSNorm ----------------
__global__ __launch_bounds__(256) void rmsnorm_kernel(
    const float* __restrict__ x, const float* __restrict__ w, float* __restrict__ out)
{
    int row = blockIdx.x;
    const float4* xr = (const float4*)(x + (size_t)row * D_);
    float ss = 0.f;
    #pragma unroll 4
    for (int i = threadIdx.x; i < D_ / 4; i += 256) {
        float4 v = xr[i];
        ss += v.x * v.x + v.y * v.y + v.z * v.z + v.w * v.w;
    }
    __shared__ float red[8];
    #pragma unroll
    for (int o = 16; o; o >>= 1) ss += __shfl_xor_sync(0xffffffffu, ss, o);
    if ((threadIdx.x & 31) == 0) red[threadIdx.x >> 5] = ss;
    __syncthreads();
    if (threadIdx.x == 0) {
        float t = 0.f;
        #pragma unroll
        for (int i = 0; i < 8; i++) t += red[i];
        red[0] = rsqrtf(t / (float)D_ + 1e-5f);
    }
    __syncthreads();
    float inv = red[0];
    const float4* wr = (const float4*)w;
    float4* o4 = (float4*)(out + (size_t)row * D_);
    for (int i = threadIdx.x; i < D_ / 4; i += 256) {
        float4 v = xr[i], wv = wr[i];
        v.x = v.x * inv * wv.x;
        v.y = v.y * inv * wv.y;
        v.z = v.z * inv * wv.z;
        v.w = v.w * inv * wv.w;
        o4[i] = v;
    }
}

// ---------------- RoPE (q and k in place) ----------------
__global__ void rope_kernel(float* __restrict__ q, float* __restrict__ k)
{
    int s = blockIdx.x;
    int j = threadIdx.x;   // 0..63 pair index
    float inv = (float)exp((double)j * -0.14391156831212787);
    float ang = (float)s * inv;
    float sn, cs;
    sincosf(ang, &sn, &cs);
    #pragma unroll 4
    for (int h = 0; h < H_; h++) {
        size_t base = ((size_t)s * H_ + h) * HD_ + 2 * j;
        float q1 = q[base], q2 = q[base + 1];
        q[base]     = q1 * cs - q2 * sn;
        q[base + 1] = q1 * sn + q2 * cs;
        float k1 = k[base], k2 = k[base + 1];
        k[base]     = k1 * cs - k2 * sn;
        k[base + 1] = k1 * sn + k2 * cs;
    }
}

// ---------------- Fused causal attention (flash style, fp32 SIMT) ----------------
#define QS_STRIDE 129
#define VS_STRIDE 132
#define SS_STRIDE 65
#define ATTN_SMEM ((2 * 64 * QS_STRIDE + 64 * VS_STRIDE + 64 * SS_STRIDE + 3 * 64) * 4)

__global__ __launch_bounds__(256) void attn_kernel(
    const float* __restrict__ Q, const float* __restrict__ Kg,
    const float* __restrict__ Vg, float* __restrict__ O)
{
    extern __shared__ float sm[];
    float* Qs   = sm;
    float* Ks   = Qs + 64 * QS_STRIDE;
    float* Vs   = Ks + 64 * QS_STRIDE;
    float* Ss   = Vs + 64 * VS_STRIDE;
    float* m_sh = Ss + 64 * SS_STRIDE;
    float* l_sh = m_sh + 64;
    float* a_sh = l_sh + 64;

    int tid = threadIdx.x;
    int h   = blockIdx.y;
    int bq  = gridDim.x - 1 - blockIdx.x;
    int q0  = bq * 64;
    int tr  = tid >> 4;
    int tc  = tid & 15;

    for (int idx = tid; idx < 64 * 32; idx += 256) {
        int r = idx >> 5, c = (idx & 31) << 2;
        float4 v = *(const float4*)(Q + (size_t)(q0 + r) * D_ + h * HD_ + c);
        float* p = Qs + r * QS_STRIDE + c;
        p[0] = v.x; p[1] = v.y; p[2] = v.z; p[3] = v.w;
    }
    if (tid < 64) { m_sh[tid] = -INFINITY; l_sh[tid] = 0.f; }
    float Oa[4][8] = {};
    __syncthreads();

    const float scale = 0.08838834764831845f;

    for (int kt = 0; kt <= bq; kt++) {
        int k0 = kt * 64;
        for (int idx = tid; idx < 64 * 32; idx += 256) {
            int r = idx >> 5, c = (idx & 31) << 2;
            float4 kv = *(const float4*)(Kg + (size_t)(k0 + r) * D_ + h * HD_ + c);
            float* kp = Ks + r * QS_STRIDE + c;
            kp[0] = kv.x; kp[1] = kv.y; kp[2] = kv.z; kp[3] = kv.w;
            float4 vv = *(const float4*)(Vg + (size_t)(k0 + r) * D_ + h * HD_ + c);
            *(float4*)(Vs + r * VS_STRIDE + c) = vv;
        }
        __syncthreads();

        float sacc[4][4] = {};
        #pragma unroll 4
        for (int kk = 0; kk < HD_; kk++) {
            float qv[4], kv[4];
            #pragma unroll
            for (int i = 0; i < 4; i++) qv[i] = Qs[(tr * 4 + i) * QS_STRIDE + kk];
            #pragma unroll
            for (int j = 0; j < 4; j++) kv[j] = Ks[(tc * 4 + j) * QS_STRIDE + kk];
            #pragma unroll
            for (int i = 0; i < 4; i++)
                #pragma unroll
                for (int j = 0; j < 4; j++)
                    sacc[i][j] = fmaf(qv[i], kv[j], sacc[i][j]);
        }
        bool diag = (kt == bq);
        #pragma unroll
        for (int i = 0; i < 4; i++)
            #pragma unroll
            for (int j = 0; j < 4; j++) {
                float v = sacc[i][j] * scale;
                if (diag && (k0 + tc * 4 + j) > (q0 + tr * 4 + i)) v = -1e30f;
                Ss[(tr * 4 + i) * SS_STRIDE + tc * 4 + j] = v;
            }
        __syncthreads();

        if (tid < 64) {
            float mold = m_sh[tid], mx = mold;
            float* Sr = Ss + tid * SS_STRIDE;
            #pragma unroll 8
            for (int j = 0; j < 64; j++) mx = fmaxf(mx, Sr[j]);
            float al = __expf(mold - mx);
            float sum = 0.f;
            #pragma unroll 8
            for (int j = 0; j < 64; j++) { float p = __expf(Sr[j] - mx); Sr[j] = p; sum += p; }
            l_sh[tid] = l_sh[tid] * al + sum;
            m_sh[tid] = mx;
            a_sh[tid] = al;
        }
        __syncthreads();

        #pragma unroll
        for (int i = 0; i < 4; i++) {
            float a = a_sh[tr * 4 + i];
            #pragma unroll
            for (int j = 0; j < 8; j++) Oa[i][j] *= a;
        }
        #pragma unroll 2
        for (int kk = 0; kk < 64; kk++) {
            float pv[4], vv[8];
            #pragma unroll
            for (int i = 0; i < 4; i++) pv[i] = Ss[(tr * 4 + i) * SS_STRIDE + kk];
            *(float4*)(vv)     = *(float4*)(Vs + kk * VS_STRIDE + tc * 8);
            *(float4*)(vv + 4) = *(float4*)(Vs + kk * VS_STRIDE + tc * 8 + 4);
            #pragma unroll
            for (int i = 0; i < 4; i++)
                #pragma unroll
                for (int j = 0; j < 8; j++)
                    Oa[i][j] = fmaf(pv[i], vv[j], Oa[i][j]);
        }
        __syncthreads();
    }

    #pragma unroll
    for (int i = 0; i < 4; i++) {
        float inv = 1.0f / l_sh[tr * 4 + i];
        float* op = O + (size_t)(q0 + tr * 4 + i) * D_ + h * HD_ + tc * 8;
        float4 v0 = make_float4(Oa[i][0] * inv, Oa[i][1] * inv, Oa[i][2] * inv, Oa[i][3] * inv);
        float4 v1 = make_float4(Oa[i][4] * inv, Oa[i][5] * inv, Oa[i][6] * inv, Oa[i][7] * inv);
        *(float4*)(op)     = v0;
        *(float4*)(op + 4) = v1;
    }
}

// ---------------- SiLU(gate) * up, in place into gate ----------------
__global__ void silu_mul_kernel(float* __restrict__ g, const float* __restrict__ u, int n4)
{
    int i = blockIdx.x * blockDim.x + threadIdx.x;
    if (i < n4) {
        float4 gv = ((const float4*)g)[i];
        float4 uv = ((const float4*)u)[i];
        gv.x = gv.x / (1.f + __expf(-gv.x)) * uv.x;
        gv.y = gv.y / (1.f + __expf(-gv.y)) * uv.y;
        gv.z = gv.z / (1.f + __expf(-gv.z)) * uv.z;
        gv.w = gv.w / (1.f + __expf(-gv.w)) * uv.w;
        ((float4*)g)[i] = gv;
    }
}

// ---------------- launch ----------------
extern "C" void kernel_launch(void* const* d_in, const int* in_sizes, int n_in,
                              void* d_out, int out_size)
{
    const float* x      = (const float*)d_in[0];
    const float* ln_w   = (const float*)d_in[1];
    const float* ffln_w = (const float*)d_in[2];
    const float* wq     = (const float*)d_in[3];
    const float* wk     = (const float*)d_in[4];
    const float* wv     = (const float*)d_in[5];
    const float* wo     = (const float*)d_in[6];
    const float* wg     = (const float*)d_in[7];
    const float* w1     = (const float*)d_in[8];
    const float* w2     = (const float*)d_in[9];
    float* out = (float*)d_out;

    float *xn, *q, *k, *v, *attn, *x2, *xn2, *gate, *up;
    cudaGetSymbolAddress((void**)&xn,   g_xn);
    cudaGetSymbolAddress((void**)&q,    g_q);
    cudaGetSymbolAddress((void**)&k,    g_k);
    cudaGetSymbolAddress((void**)&v,    g_v);
    cudaGetSymbolAddress((void**)&attn, g_attn);
    cudaGetSymbolAddress((void**)&x2,   g_x2);
    cudaGetSymbolAddress((void**)&xn2,  g_xn2);
    cudaGetSymbolAddress((void**)&gate, g_gate);
    cudaGetSymbolAddress((void**)&up,   g_up);

    __half *wqt_h, *wqt_l, *wkt_h, *wkt_l, *wvt_h, *wvt_l, *wot_h, *wot_l;
    __half *wgt_h, *wgt_l, *w1t_h, *w1t_l, *w2t_h, *w2t_l, *a_h, *a_l;
    cudaGetSymbolAddress((void**)&wqt_h, g_wqt_h); cudaGetSymbolAddress((void**)&wqt_l, g_wqt_l);
    cudaGetSymbolAddress((void**)&wkt_h, g_wkt_h); cudaGetSymbolAddress((void**)&wkt_l, g_wkt_l);
    cudaGetSymbolAddress((void**)&wvt_h, g_wvt_h); cudaGetSymbolAddress((void**)&wvt_l, g_wvt_l);
    cudaGetSymbolAddress((void**)&wot_h, g_wot_h); cudaGetSymbolAddress((void**)&wot_l, g_wot_l);
    cudaGetSymbolAddress((void**)&wgt_h, g_wgt_h); cudaGetSymbolAddress((void**)&wgt_l, g_wgt_l);
    cudaGetSymbolAddress((void**)&w1t_h, g_w1t_h); cudaGetSymbolAddress((void**)&w1t_l, g_w1t_l);
    cudaGetSymbolAddress((void**)&w2t_h, g_w2t_h); cudaGetSymbolAddress((void**)&w2t_l, g_w2t_l);
    cudaGetSymbolAddress((void**)&a_h, g_a_h);     cudaGetSymbolAddress((void**)&a_l, g_a_l);

    cudaFuncSetAttribute(attn_kernel, cudaFuncAttributeMaxDynamicSharedMemorySize, ATTN_SMEM);
    cudaFuncSetAttribute(hgemm<false>, cudaFuncAttributeMaxDynamicSharedMemorySize, HGEMM_SMEM);
    cudaFuncSetAttribute(hgemm<true>,  cudaFuncAttributeMaxDynamicSharedMemorySize, HGEMM_SMEM);

    // weight prep: transpose + hi/lo split (fp16)
    dim3 wt(32, 8);
    wsplit_kernel<<<dim3(D_ / 32, D_ / 32), wt>>>(wq, wqt_h, wqt_l, D_, D_);
    wsplit_kernel<<<dim3(D_ / 32, D_ / 32), wt>>>(wk, wkt_h, wkt_l, D_, D_);
    wsplit_kernel<<<dim3(D_ / 32, D_ / 32), wt>>>(wv, wvt_h, wvt_l, D_, D_);
    wsplit_kernel<<<dim3(D_ / 32, D_ / 32), wt>>>(wo, wot_h, wot_l, D_, D_);
    wsplit_kernel<<<dim3(FF_ / 32, D_ / 32), wt>>>(wg, wgt_h, wgt_l, D_, FF_);
    wsplit_kernel<<<dim3(FF_ / 32, D_ / 32), wt>>>(w1, w1t_h, w1t_l, D_, FF_);
    wsplit_kernel<<<dim3(D_ / 32, FF_ / 32), wt>>>(w2, w2t_h, w2t_l, FF_, D_);

    // xn = rmsnorm(x, ln_w); split
    rmsnorm_kernel<<<S_, 256>>>(x, ln_w, xn);
    int nsd = (S_ * D_) / 4;
    asplit_kernel<<<(nsd + 255) / 256, 256>>>(xn, a_h, a_l, nsd);

    // q,k,v projections
    dim3 gdd(S_ / 128, D_ / 128);
    hgemm<false><<<gdd, 256, HGEMM_SMEM>>>(S_, D_, D_, a_h, a_l, wqt_h, wqt_l, nullptr, q);
    hgemm<false><<<gdd, 256, HGEMM_SMEM>>>(S_, D_, D_, a_h, a_l, wkt_h, wkt_l, nullptr, k);
    hgemm<false><<<gdd, 256, HGEMM_SMEM>>>(S_, D_, D_, a_h, a_l, wvt_h, wvt_l, nullptr, v);

    // rope + attention
    rope_kernel<<<S_, 64>>>(q, k);
    attn_kernel<<<dim3(S_ / 64, H_), 256, ATTN_SMEM>>>(q, k, v, attn);

    // x2 = attn @ wo + x
    asplit_kernel<<<(nsd + 255) / 256, 256>>>(attn, a_h, a_l, nsd);
    hgemm<true><<<gdd, 256, HGEMM_SMEM>>>(S_, D_, D_, a_h, a_l, wot_h, wot_l, x, x2);

    // xn2 = rmsnorm(x2, ff_ln_w); split
    rmsnorm_kernel<<<S_, 256>>>(x2, ffln_w, xn2);
    asplit_kernel<<<(nsd + 255) / 256, 256>>>(xn2, a_h, a_l, nsd);

    // gate/up projections
    dim3 gdf(S_ / 128, FF_ / 128);
    hgemm<false><<<gdf, 256, HGEMM_SMEM>>>(S_, FF_, D_, a_h, a_l, wgt_h, wgt_l, nullptr, gate);
    hgemm<false><<<gdf, 256, HGEMM_SMEM>>>(S_, FF_, D_, a_h, a_l, w1t_h, w1t_l, nullptr, up);

    // h = silu(gate) * up (into gate); split
    int nsf = (S_ * FF_) / 4;
    silu_mul_kernel<<<(nsf + 255) / 256, 256>>>(gate, up, nsf);
    asplit_kernel<<<(nsf + 255) / 256, 256>>>(gate, a_h, a_l, nsf);

    // out = h @ w2 + x2
    hgemm<true><<<dim3(S_ / 128, D_ / 128), 256, HGEMM_SMEM>>>(S_, D_, FF_, a_h, a_l, w2t_h, w2t_l, x2, out);
}